// round 5
// baseline (speedup 1.0000x reference)
#include <cuda_runtime.h>
#include <cstdint>

#define EPS_F 1e-6f
#define S_DIM 2048
#define H_DIM 12
#define W_DIM 32
#define MAXSEG 33
#define PLANE ((size_t)S_DIM * S_DIM)

#define NBLOCKS 592   // 4 CTAs/SM * 148 SMs, persistent
#define NTHREADS 256  // each thread: 8 j (two float4 groups), block owns a row

// ---------------------------------------------------------------------------
// Single fused persistent kernel.
// Phase 1 (per block, smem): A-table (2048 logf), hinge sort, PWL coefficients.
// Phase 2: grid-stride rows; per thread 8 j = {4t..4t+3} u {1024+4t..+3};
//          ONE hinge search per thread per row (bracketed by min/max nd),
//          12 heads x 2 coalesced float4 streaming stores.
// ---------------------------------------------------------------------------
__global__ __launch_bounds__(NTHREADS, 4) void fire_all(
        const float* __restrict__ w1,
        const float* __restrict__ b1,
        const float* __restrict__ w2,
        const float* __restrict__ b2,
        const float* __restrict__ cp,
        const float* __restrict__ lmp,
        const float* __restrict__ ilp,
        float* __restrict__ out) {
    __shared__ float sA[S_DIM];                  // log(|d|*c + 1 + eps)
    __shared__ float s_hinge[MAXSEG];            // sorted hinges, +inf padded (33)
    __shared__ float s_slope[MAXSEG * H_DIM];
    __shared__ float s_icpt [MAXSEG * H_DIM];
    __shared__ float shW1[W_DIM], shB1[W_DIM], shT[W_DIM], shH[W_DIM + 1];
    __shared__ int   shNh;

    const float INFF = __int_as_float(0x7f800000);
    const int t = threadIdx.x;

    const float c   = __ldg(cp);
    const float thr = fabsf(__ldg(lmp) * __ldg(ilp));

    // ---- A table: 8 entries per thread ----
    #pragma unroll
    for (int r = 0; r < S_DIM / NTHREADS; r++) {
        int e = t + r * NTHREADS;
        float abs_rel = (float)e + EPS_F;
        sA[e] = logf((abs_rel * c + 1.0f) + EPS_F);
    }

    // ---- hinge positions + rank sort ----
    if (t < W_DIM) { shW1[t] = w1[t]; shB1[t] = b1[t]; }
    __syncthreads();
    if (t < W_DIM) {
        bool valid = (shW1[t] != 0.0f);            // w1==0 -> no hinge
        shT[t] = valid ? (-shB1[t] / shW1[t]) : INFF;
    }
    __syncthreads();
    if (t < W_DIM) {
        float tv = shT[t];
        int rank = 0;
        #pragma unroll
        for (int v = 0; v < W_DIM; v++) {
            float o = shT[v];
            rank += (o < tv) || (o == tv && v < t);
        }
        shH[rank] = tv;
        if (t == 0) {
            int n = 0;
            for (int v = 0; v < W_DIM; v++) n += (shW1[v] != 0.0f);
            shNh = n;
        }
    }
    __syncthreads();
    const int nh = shNh;
    if (t < MAXSEG) s_hinge[t] = (t < nh) ? shH[t] : INFF;   // [32] = +inf too

    // ---- coefficients: (segment, head) pairs, strided over threads ----
    for (int idx = t; idx < (nh + 1) * H_DIM; idx += NTHREADS) {
        int s = idx / H_DIM;
        int h = idx - s * H_DIM;
        float x;                                    // interior point of segment s
        if (nh == 0)      x = 0.0f;
        else if (s == 0)  x = shH[0] - 1.0f;
        else if (s == nh) x = shH[nh - 1] + 1.0f;
        else              x = 0.5f * (shH[s - 1] + shH[s]);

        float sl = 0.0f, ic = __ldg(&b2[h]);
        #pragma unroll
        for (int w = 0; w < W_DIM; w++) {
            float w1v = shW1[w], b1v = shB1[w];
            if (w1v * x + b1v > 0.0f) {             // unit active on this segment
                float w2v = __ldg(&w2[h * W_DIM + w]);
                sl = fmaf(w2v, w1v, sl);
                ic = fmaf(w2v, b1v, ic);
            }
        }
        s_slope[idx] = sl;
        s_icpt [idx] = ic;
    }
    __syncthreads();

    // ---- main fill ----
    const int jA = t * 4;            // group A: coalesced float4
    const int jB = t * 4 + 1024;     // group B: coalesced float4
    for (int i = blockIdx.x; i < S_DIM; i += NBLOCKS) {
        float pos_norm = fmaxf((float)i, thr) + EPS_F;
        float invB = 1.0f / logf((fabsf(c * pos_norm) + 1.0f) + EPS_F);

        float nd[8];
        #pragma unroll
        for (int k = 0; k < 4; k++) nd[k]     = sA[abs(i - (jA + k))] * invB;
        #pragma unroll
        for (int k = 0; k < 4; k++) nd[4 + k] = sA[abs(i - (jB + k))] * invB;

        // bracket all 8 values (handles V-shape near diagonal automatically)
        float lo01 = fminf(nd[0], nd[1]), lo23 = fminf(nd[2], nd[3]);
        float lo45 = fminf(nd[4], nd[5]), lo67 = fminf(nd[6], nd[7]);
        float hi01 = fmaxf(nd[0], nd[1]), hi23 = fmaxf(nd[2], nd[3]);
        float hi45 = fmaxf(nd[4], nd[5]), hi67 = fmaxf(nd[6], nd[7]);
        float ndlo = fminf(fminf(lo01, lo23), fminf(lo45, lo67));
        float ndhi = fmaxf(fmaxf(hi01, hi23), fmaxf(hi45, hi67));

        // one lower_bound over 32 sorted (+inf padded) hinges
        int lo = 0, hi = 32;
        #pragma unroll
        for (int it = 0; it < 5; it++) {
            int mid = (lo + hi) >> 1;
            bool ge = (ndlo >= s_hinge[mid]);
            lo = ge ? mid + 1 : lo;
            hi = ge ? hi : mid;
        }
        const int seg = lo;
        const bool uni = (ndhi < s_hinge[seg]);   // whole window in one segment

        const size_t baseA = (size_t)i * S_DIM + jA;
        if (uni) {
            const float* sl = &s_slope[seg * H_DIM];
            const float* ic = &s_icpt [seg * H_DIM];
            #pragma unroll
            for (int h = 0; h < H_DIM; h++) {
                float s = sl[h], b = ic[h];
                float4 vA, vB;
                vA.x = fmaf(nd[0], s, b); vA.y = fmaf(nd[1], s, b);
                vA.z = fmaf(nd[2], s, b); vA.w = fmaf(nd[3], s, b);
                vB.x = fmaf(nd[4], s, b); vB.y = fmaf(nd[5], s, b);
                vB.z = fmaf(nd[6], s, b); vB.w = fmaf(nd[7], s, b);
                float* p = out + (size_t)h * PLANE + baseA;
                __stcs(reinterpret_cast<float4*>(p), vA);
                __stcs(reinterpret_cast<float4*>(p + 1024), vB);
            }
        } else {
            // rare: window crosses a hinge -> per-element segment
            int sg[8];
            #pragma unroll
            for (int k = 0; k < 8; k++) {
                int l2 = 0, h2 = 32;
                #pragma unroll
                for (int it = 0; it < 5; it++) {
                    int mid = (l2 + h2) >> 1;
                    bool ge = (nd[k] >= s_hinge[mid]);
                    l2 = ge ? mid + 1 : l2;
                    h2 = ge ? h2 : mid;
                }
                sg[k] = l2 * H_DIM;
            }
            #pragma unroll
            for (int h = 0; h < H_DIM; h++) {
                float4 vA, vB;
                vA.x = fmaf(nd[0], s_slope[sg[0] + h], s_icpt[sg[0] + h]);
                vA.y = fmaf(nd[1], s_slope[sg[1] + h], s_icpt[sg[1] + h]);
                vA.z = fmaf(nd[2], s_slope[sg[2] + h], s_icpt[sg[2] + h]);
                vA.w = fmaf(nd[3], s_slope[sg[3] + h], s_icpt[sg[3] + h]);
                vB.x = fmaf(nd[4], s_slope[sg[4] + h], s_icpt[sg[4] + h]);
                vB.y = fmaf(nd[5], s_slope[sg[5] + h], s_icpt[sg[5] + h]);
                vB.z = fmaf(nd[6], s_slope[sg[6] + h], s_icpt[sg[6] + h]);
                vB.w = fmaf(nd[7], s_slope[sg[7] + h], s_icpt[sg[7] + h]);
                float* p = out + (size_t)h * PLANE + baseA;
                __stcs(reinterpret_cast<float4*>(p), vA);
                __stcs(reinterpret_cast<float4*>(p + 1024), vB);
            }
        }
    }
}

// ---------------------------------------------------------------------------
// Inputs (metadata order): x, w1, b1, w2, b2, c, L_multiplier, init_L
// ---------------------------------------------------------------------------
extern "C" void kernel_launch(void* const* d_in, const int* in_sizes, int n_in,
                              void* d_out, int out_size) {
    const float* w1 = (const float*)d_in[1];
    const float* b1 = (const float*)d_in[2];
    const float* w2 = (const float*)d_in[3];
    const float* b2 = (const float*)d_in[4];
    const float* c  = (const float*)d_in[5];
    const float* lm = (const float*)d_in[6];
    const float* il = (const float*)d_in[7];
    float* out = (float*)d_out;

    fire_all<<<NBLOCKS, NTHREADS>>>(w1, b1, w2, b2, c, lm, il, out);
}

// round 7
// speedup vs baseline: 1.4292x; 1.4292x over previous
#include <cuda_runtime.h>
#include <cstdint>

#define EPS_F 1e-6f
#define S_DIM 2048
#define H_DIM 12
#define W_DIM 32
#define MAXSEG 33
#define PLANE ((size_t)S_DIM * S_DIM)

// -------- persistent scratch (device globals: no allocation allowed) --------
__device__ float g_A[S_DIM];        // log(|d|*c + 1 + eps), d = |i-j|
__device__ float g_invB[S_DIM];     // 1 / log(|c*pos_norm(i)| + 1 + eps)
__device__ float g_hinge[MAXSEG];   // sorted hinges, +inf padded (33 entries)
__device__ float g_slope[MAXSEG * H_DIM];
__device__ float g_icpt [MAXSEG * H_DIM];

// ---------------------------------------------------------------------------
// Parallel setup: 33 blocks x 128 threads.
//   blocks 0-7 : g_A   (256 entries each)
//   blocks 8-15: g_invB(256 entries each)
//   all blocks : redundant hinge sort (trivial)
//   block b    : coefficients of segment b (12 heads, one per thread)
// ---------------------------------------------------------------------------
__global__ __launch_bounds__(128) void fire_setup(
        const float* __restrict__ w1, const float* __restrict__ b1,
        const float* __restrict__ w2, const float* __restrict__ b2,
        const float* __restrict__ cp, const float* __restrict__ lmp,
        const float* __restrict__ ilp) {
    __shared__ float shW1[W_DIM], shB1[W_DIM], shT[W_DIM], shH[W_DIM + 1];
    __shared__ int   shNh;
    const float INFF = __int_as_float(0x7f800000);
    const int t = threadIdx.x;
    const int b = blockIdx.x;

    const float c   = __ldg(cp);
    const float thr = fabsf(__ldg(lmp) * __ldg(ilp));

    // ---- tables ----
    if (b < 8) {
        #pragma unroll
        for (int r = 0; r < 2; r++) {
            int e = b * 256 + t + r * 128;
            float abs_rel = (float)e + EPS_F;
            g_A[e] = logf((abs_rel * c + 1.0f) + EPS_F);
        }
    } else if (b < 16) {
        #pragma unroll
        for (int r = 0; r < 2; r++) {
            int e = (b - 8) * 256 + t + r * 128;
            float pos_norm = fmaxf((float)e, thr) + EPS_F;
            g_invB[e] = 1.0f / logf((fabsf(c * pos_norm) + 1.0f) + EPS_F);
        }
    }

    // ---- hinge sort (every block, cheap) ----
    if (t < W_DIM) { shW1[t] = w1[t]; shB1[t] = b1[t]; }
    __syncthreads();
    if (t < W_DIM) {
        bool valid = (shW1[t] != 0.0f);
        shT[t] = valid ? (-shB1[t] / shW1[t]) : INFF;
    }
    __syncthreads();
    if (t < W_DIM) {
        float tv = shT[t];
        int rank = 0;
        #pragma unroll
        for (int v = 0; v < W_DIM; v++) {
            float o = shT[v];
            rank += (o < tv) || (o == tv && v < t);
        }
        shH[rank] = tv;
        if (t == 0) {
            int n = 0;
            for (int v = 0; v < W_DIM; v++) n += (shW1[v] != 0.0f);
            shNh = n;
        }
    }
    __syncthreads();
    const int nh = shNh;
    if (b == 0 && t < MAXSEG) g_hinge[t] = (t < nh) ? shH[t] : INFF;

    // ---- segment b coefficients ----
    if (b <= nh && t < H_DIM) {
        float x;
        if (nh == 0)      x = 0.0f;
        else if (b == 0)  x = shH[0] - 1.0f;
        else if (b == nh) x = shH[nh - 1] + 1.0f;
        else              x = 0.5f * (shH[b - 1] + shH[b]);

        float sl = 0.0f, ic = __ldg(&b2[t]);
        #pragma unroll
        for (int w = 0; w < W_DIM; w++) {
            float w1v = shW1[w], b1v = shB1[w];
            if (w1v * x + b1v > 0.0f) {
                float w2v = __ldg(&w2[t * W_DIM + w]);
                sl = fmaf(w2v, w1v, sl);
                ic = fmaf(w2v, b1v, ic);
            }
        }
        g_slope[b * H_DIM + t] = sl;
        g_icpt [b * H_DIM + t] = ic;
    }
}

// ---------------------------------------------------------------------------
// Main fill: block = 256 threads, 4 CONTIGUOUS j per thread.
// One bracketed hinge search per thread (min/max of 4 nd), fallback rare.
// 12 float4 streaming stores per thread.
// ---------------------------------------------------------------------------
__global__ __launch_bounds__(256) void fire_main(float* __restrict__ out) {
    __shared__ float s_hinge[MAXSEG];
    __shared__ float s_slope[MAXSEG * H_DIM];
    __shared__ float s_icpt [MAXSEG * H_DIM];

    const int tid = threadIdx.x;
    for (int idx = tid; idx < MAXSEG * H_DIM; idx += 256) {
        s_slope[idx] = g_slope[idx];
        s_icpt [idx] = g_icpt [idx];
    }
    if (tid < MAXSEG) s_hinge[tid] = g_hinge[tid];
    __syncthreads();

    const int i  = blockIdx.y;
    const int j0 = blockIdx.x * 1024 + tid * 4;
    const float invB = __ldg(&g_invB[i]);

    float nd[4];
    #pragma unroll
    for (int k = 0; k < 4; k++)
        nd[k] = __ldg(&g_A[abs(i - (j0 + k))]) * invB;

    // bracket the contiguous window (handles V-shape at diagonal too)
    float ndlo = fminf(fminf(nd[0], nd[1]), fminf(nd[2], nd[3]));
    float ndhi = fmaxf(fmaxf(nd[0], nd[1]), fmaxf(nd[2], nd[3]));

    // one lower_bound over 32 sorted (+inf padded) hinges
    int lo = 0, hi = 32;
    #pragma unroll
    for (int it = 0; it < 5; it++) {
        int mid = (lo + hi) >> 1;
        bool ge = (ndlo >= s_hinge[mid]);
        lo = ge ? mid + 1 : lo;
        hi = ge ? hi : mid;
    }
    const int seg = lo;
    const bool uni = (ndhi < s_hinge[seg]);   // whole window inside one segment

    const size_t base = (size_t)i * S_DIM + j0;
    if (uni) {
        const float* sl = &s_slope[seg * H_DIM];
        const float* ic = &s_icpt [seg * H_DIM];
        float* p = out + base;
        #pragma unroll
        for (int h = 0; h < H_DIM; h++) {
            float s = sl[h], bb = ic[h];
            float4 v;
            v.x = fmaf(nd[0], s, bb);
            v.y = fmaf(nd[1], s, bb);
            v.z = fmaf(nd[2], s, bb);
            v.w = fmaf(nd[3], s, bb);
            __stcs(reinterpret_cast<float4*>(p), v);
            p += PLANE;
        }
    } else {
        // rare: window crosses a hinge -> per-element segment
        int sg[4];
        #pragma unroll
        for (int k = 0; k < 4; k++) {
            int l2 = 0, h2 = 32;
            #pragma unroll
            for (int it = 0; it < 5; it++) {
                int mid = (l2 + h2) >> 1;
                bool ge = (nd[k] >= s_hinge[mid]);
                l2 = ge ? mid + 1 : l2;
                h2 = ge ? h2 : mid;
            }
            sg[k] = l2 * H_DIM;
        }
        float* p = out + base;
        #pragma unroll
        for (int h = 0; h < H_DIM; h++) {
            float4 v;
            v.x = fmaf(nd[0], s_slope[sg[0] + h], s_icpt[sg[0] + h]);
            v.y = fmaf(nd[1], s_slope[sg[1] + h], s_icpt[sg[1] + h]);
            v.z = fmaf(nd[2], s_slope[sg[2] + h], s_icpt[sg[2] + h]);
            v.w = fmaf(nd[3], s_slope[sg[3] + h], s_icpt[sg[3] + h]);
            __stcs(reinterpret_cast<float4*>(p), v);
            p += PLANE;
        }
    }
}

// ---------------------------------------------------------------------------
// Inputs (metadata order): x, w1, b1, w2, b2, c, L_multiplier, init_L
// ---------------------------------------------------------------------------
extern "C" void kernel_launch(void* const* d_in, const int* in_sizes, int n_in,
                              void* d_out, int out_size) {
    const float* w1 = (const float*)d_in[1];
    const float* b1 = (const float*)d_in[2];
    const float* w2 = (const float*)d_in[3];
    const float* b2 = (const float*)d_in[4];
    const float* c  = (const float*)d_in[5];
    const float* lm = (const float*)d_in[6];
    const float* il = (const float*)d_in[7];
    float* out = (float*)d_out;

    fire_setup<<<MAXSEG, 128>>>(w1, b1, w2, b2, c, lm, il);

    dim3 grid(S_DIM / 1024, S_DIM);   // (2, 2048)
    fire_main<<<grid, 256>>>(out);
}